// round 1
// baseline (speedup 1.0000x reference)
#include <cuda_runtime.h>
#include <cstdint>
#include <cstddef>

#define NNODES 100000
#define NEDGES 1600000
#define FIN 256
#define HID 64

// ---------------- device scratch (no allocations allowed) ----------------
__device__ int   g_indeg[NNODES];
__device__ int   g_outdeg[NNODES];
__device__ int   g_rowptr[NNODES + 1];
__device__ int   g_cursor[NNODES];
__device__ int   g_srcsorted[NEDGES];
__device__ float g_ns[NNODES];   // rsqrt(max(out_deg,1))
__device__ float g_nd[NNODES];   // rsqrt(max(in_deg,1))
__device__ float g_t[(size_t)NNODES * HID];
__device__ float g_h[(size_t)NNODES * HID];
__device__ float g_proj[(size_t)NNODES * HID];

// ---------------- setup kernels ----------------
__global__ void zero_deg_kernel(int n) {
    int i = blockIdx.x * blockDim.x + threadIdx.x;
    if (i < n) { g_indeg[i] = 0; g_outdeg[i] = 0; }
}

__global__ void count_kernel(const int* __restrict__ src, const int* __restrict__ dst, int e) {
    int i = blockIdx.x * blockDim.x + threadIdx.x;
    if (i < e) {
        atomicAdd(&g_outdeg[src[i]], 1);
        atomicAdd(&g_indeg[dst[i]], 1);
    }
}

// single-block exclusive scan of in_deg -> rowptr (and cursor copy)
__global__ void scan_kernel(int n) {
    __shared__ int wsum[32];
    __shared__ int s_off;
    int tid = threadIdx.x;
    if (tid == 0) s_off = 0;
    __syncthreads();
    int nIter = (n + 1023) / 1024;
    for (int it = 0; it < nIter; it++) {
        int i = it * 1024 + tid;
        int v = (i < n) ? g_indeg[i] : 0;
        int x = v;
        #pragma unroll
        for (int d = 1; d < 32; d <<= 1) {
            int y = __shfl_up_sync(0xffffffffu, x, d);
            if ((tid & 31) >= d) x += y;
        }
        if ((tid & 31) == 31) wsum[tid >> 5] = x;
        __syncthreads();
        if (tid < 32) {
            int w = wsum[tid];
            #pragma unroll
            for (int d = 1; d < 32; d <<= 1) {
                int y = __shfl_up_sync(0xffffffffu, w, d);
                if (tid >= d) w += y;
            }
            wsum[tid] = w;  // inclusive scan of warp sums
        }
        __syncthreads();
        int base = s_off;
        int warpoff = (tid >= 32) ? wsum[(tid >> 5) - 1] : 0;
        int excl = base + warpoff + x - v;
        if (i < n) { g_rowptr[i] = excl; g_cursor[i] = excl; }
        int total = wsum[31];
        __syncthreads();
        if (tid == 0) s_off = base + total;
        __syncthreads();
    }
    if (tid == 0) g_rowptr[n] = s_off;
}

__global__ void norm_kernel(int n) {
    int i = blockIdx.x * blockDim.x + threadIdx.x;
    if (i < n) {
        g_nd[i] = rsqrtf(fmaxf((float)g_indeg[i], 1.0f));
        g_ns[i] = rsqrtf(fmaxf((float)g_outdeg[i], 1.0f));
    }
}

__global__ void csr_kernel(const int* __restrict__ src, const int* __restrict__ dst, int e) {
    int i = blockIdx.x * blockDim.x + threadIdx.x;
    if (i < e) {
        int d = dst[i];
        int pos = atomicAdd(&g_cursor[d], 1);
        g_srcsorted[pos] = src[i];
    }
}

// ---------------- GEMM: C[n x 64] = op(A[n x K] @ B[K x 64]) ----------------
// mode 0: C = ns[row] * (A@B)         (pre-normalized message for scatter)
// mode 1: C = (beta? C:0) + A@B       (JK projection accumulate)
template <int K>
__global__ void __launch_bounds__(128) gemm_kernel(
    const float* __restrict__ A, int lda,
    const float* __restrict__ B,
    float* __restrict__ C,
    int mode, int beta, int n)
{
    const int TM = 128, KC = 32;
    __shared__ float Ash[KC][TM + 4];  // transposed: [k][row]
    __shared__ float Bsh[KC][64 + 4];  // [k][col]
    int row0 = blockIdx.x * TM;
    int tid = threadIdx.x;
    int tr = tid >> 3;   // 0..15 -> rows tr*8 .. tr*8+7
    int tc = tid & 7;    // 0..7  -> cols tc*8 .. tc*8+7
    float acc[8][8];
    #pragma unroll
    for (int r = 0; r < 8; r++)
        #pragma unroll
        for (int c = 0; c < 8; c++) acc[r][c] = 0.f;

    for (int kc = 0; kc < K; kc += KC) {
        // stage A chunk (128 rows x 32 k), transposed into shared
        #pragma unroll
        for (int i = 0; i < 8; i++) {
            int flat = tid + i * 128;       // float4 id, 0..1023
            int row = flat >> 3;
            int k4 = flat & 7;
            float4 v = make_float4(0.f, 0.f, 0.f, 0.f);
            int gr = row0 + row;
            if (gr < n) v = *(const float4*)(A + (size_t)gr * lda + kc + k4 * 4);
            Ash[k4 * 4 + 0][row] = v.x;
            Ash[k4 * 4 + 1][row] = v.y;
            Ash[k4 * 4 + 2][row] = v.z;
            Ash[k4 * 4 + 3][row] = v.w;
        }
        // stage B chunk (32 x 64)
        #pragma unroll
        for (int i = 0; i < 4; i++) {
            int flat = tid + i * 128;       // float4 id, 0..511
            int k = flat >> 4;
            int c4 = flat & 15;
            *(float4*)&Bsh[k][c4 * 4] = *(const float4*)(B + (size_t)(kc + k) * 64 + c4 * 4);
        }
        __syncthreads();
        #pragma unroll
        for (int k = 0; k < KC; k++) {
            float a[8], bb[8];
            *(float4*)&a[0]  = *(const float4*)&Ash[k][tr * 8];
            *(float4*)&a[4]  = *(const float4*)&Ash[k][tr * 8 + 4];
            *(float4*)&bb[0] = *(const float4*)&Bsh[k][tc * 8];
            *(float4*)&bb[4] = *(const float4*)&Bsh[k][tc * 8 + 4];
            #pragma unroll
            for (int r = 0; r < 8; r++)
                #pragma unroll
                for (int c = 0; c < 8; c++)
                    acc[r][c] = fmaf(a[r], bb[c], acc[r][c]);
        }
        __syncthreads();
    }

    #pragma unroll
    for (int r = 0; r < 8; r++) {
        int gr = row0 + tr * 8 + r;
        if (gr >= n) break;
        float* cp = C + (size_t)gr * 64 + tc * 8;
        float4 v0, v1;
        if (mode == 0) {
            float s = g_ns[gr];
            v0 = make_float4(s * acc[r][0], s * acc[r][1], s * acc[r][2], s * acc[r][3]);
            v1 = make_float4(s * acc[r][4], s * acc[r][5], s * acc[r][6], s * acc[r][7]);
        } else {
            v0 = make_float4(acc[r][0], acc[r][1], acc[r][2], acc[r][3]);
            v1 = make_float4(acc[r][4], acc[r][5], acc[r][6], acc[r][7]);
            if (beta) {
                float4 o0 = *(const float4*)cp;
                float4 o1 = *(const float4*)(cp + 4);
                v0.x += o0.x; v0.y += o0.y; v0.z += o0.z; v0.w += o0.w;
                v1.x += o1.x; v1.y += o1.y; v1.z += o1.z; v1.w += o1.w;
            }
        }
        *(float4*)cp = v0;
        *(float4*)(cp + 4) = v1;
    }
}

// ---------------- CSR gather-aggregate (fused pointwise epilogue) ----------------
// mode 0: hout[d] = relu(nd[d] * sum_{s in N(d)} tin[s] + bias)
// mode 1: hout[d] = sum + bias        (final output, bias = bout)
__global__ void __launch_bounds__(256) aggregate_kernel(
    const float* __restrict__ tin, float* __restrict__ hout,
    const float* __restrict__ bias, int mode, int n)
{
    int g = blockIdx.x * 256 + threadIdx.x;
    int node = g >> 4;
    int lane = g & 15;
    if (node >= n) return;
    int beg = g_rowptr[node];
    int end = g_rowptr[node + 1];
    float4 acc = make_float4(0.f, 0.f, 0.f, 0.f);
    for (int e = beg; e < end; e++) {
        int s = __ldg(&g_srcsorted[e]);
        float4 v = *(const float4*)(tin + (size_t)s * 64 + lane * 4);
        acc.x += v.x; acc.y += v.y; acc.z += v.z; acc.w += v.w;
    }
    float4 bb = *(const float4*)(bias + lane * 4);
    float4 o;
    if (mode == 0) {
        float ndv = g_nd[node];
        o.x = fmaxf(fmaf(acc.x, ndv, bb.x), 0.f);
        o.y = fmaxf(fmaf(acc.y, ndv, bb.y), 0.f);
        o.z = fmaxf(fmaf(acc.z, ndv, bb.z), 0.f);
        o.w = fmaxf(fmaf(acc.w, ndv, bb.w), 0.f);
    } else {
        o.x = acc.x + bb.x; o.y = acc.y + bb.y;
        o.z = acc.z + bb.z; o.w = acc.w + bb.w;
    }
    *(float4*)(hout + (size_t)node * 64 + lane * 4) = o;
}

// ---------------- host ----------------
extern "C" void kernel_launch(void* const* d_in, const int* in_sizes, int n_in,
                              void* d_out, int out_size)
{
    const float* feats = (const float*)d_in[0];
    const int*   src   = (const int*)d_in[1];
    const int*   dst   = (const int*)d_in[2];
    const float* W[5];
    const float* b[5];
    for (int i = 0; i < 5; i++) {
        W[i] = (const float*)d_in[3 + 2 * i];
        b[i] = (const float*)d_in[4 + 2 * i];
    }
    const float* Wout = (const float*)d_in[13];
    const float* bout = (const float*)d_in[14];
    float* out = (float*)d_out;

    int n = in_sizes[0] / FIN;   // 100000
    int e = in_sizes[1];         // 1600000

    float *t, *h, *proj;
    cudaGetSymbolAddress((void**)&t, g_t);
    cudaGetSymbolAddress((void**)&h, g_h);
    cudaGetSymbolAddress((void**)&proj, g_proj);

    int nb256 = (n + 255) / 256;
    int eb256 = (e + 255) / 256;
    int gemm_blocks = (n + 127) / 128;
    int agg_blocks = (n * 16 + 255) / 256;

    // graph preprocessing (recomputed every call: deterministic w.r.t. inputs)
    zero_deg_kernel<<<nb256, 256>>>(n);
    count_kernel<<<eb256, 256>>>(src, dst, e);
    scan_kernel<<<1, 1024>>>(n);
    norm_kernel<<<nb256, 256>>>(n);
    csr_kernel<<<eb256, 256>>>(src, dst, e);

    // layer 0: t = ns * (feats @ W0); h = relu(nd * segsum(t) + b0)
    gemm_kernel<FIN><<<gemm_blocks, 128>>>(feats, FIN, W[0], t, 0, 0, n);
    aggregate_kernel<<<agg_blocks, 256>>>(t, h, b[0], 0, n);

    // layers 1..4: t = ns*(h@W_l); proj (+)= h@Wout_block_{l-1}; h = relu(nd*segsum(t)+b_l)
    for (int l = 1; l < 5; l++) {
        gemm_kernel<HID><<<gemm_blocks, 128>>>(h, HID, W[l], t, 0, 0, n);
        gemm_kernel<HID><<<gemm_blocks, 128>>>(h, HID, Wout + (size_t)(l - 1) * HID * 64,
                                               proj, 1, (l > 1) ? 1 : 0, n);
        aggregate_kernel<<<agg_blocks, 256>>>(t, h, b[l], 0, n);
    }
    // last JK block: proj += h5 @ Wout_block_4
    gemm_kernel<HID><<<gemm_blocks, 128>>>(h, HID, Wout + (size_t)4 * HID * 64, proj, 1, 1, n);

    // final: out = segsum(proj[src], dst) + bout
    aggregate_kernel<<<agg_blocks, 256>>>(proj, out, bout, 1, n);
}

// round 2
// speedup vs baseline: 1.0111x; 1.0111x over previous
#include <cuda_runtime.h>
#include <cstdint>
#include <cstddef>

#define NNODES 100000
#define NEDGES 1600000
#define FIN 256
#define HID 64

// ---------------- device scratch (no allocations allowed) ----------------
__device__ int   g_indeg[NNODES];
__device__ int   g_outdeg[NNODES];
__device__ int   g_rowptr[NNODES + 1];
__device__ int   g_cursor[NNODES];
__device__ int   g_srcsorted[NEDGES];
__device__ float g_ns[NNODES];   // rsqrt(max(out_deg,1))
__device__ float g_nd[NNODES];   // rsqrt(max(in_deg,1))
__device__ float g_t[(size_t)NNODES * HID];
__device__ float g_h[(size_t)NNODES * HID];
__device__ float g_proj[(size_t)NNODES * HID];

// ---------------- packed f32x2 helpers ----------------
__device__ __forceinline__ void fma2(unsigned long long& d,
                                     unsigned long long a,
                                     unsigned long long b) {
    asm("fma.rn.f32x2 %0, %1, %2, %0;" : "+l"(d) : "l"(a), "l"(b));
}
__device__ __forceinline__ float2 unpk(unsigned long long v) {
    float2 r;
    asm("mov.b64 {%0, %1}, %2;" : "=f"(r.x), "=f"(r.y) : "l"(v));
    return r;
}

// ---------------- setup kernels ----------------
__global__ void zero_deg_kernel(int n) {
    int i = blockIdx.x * blockDim.x + threadIdx.x;
    if (i < n) { g_indeg[i] = 0; g_outdeg[i] = 0; }
}

__global__ void count_kernel(const int* __restrict__ src, const int* __restrict__ dst, int e) {
    int i = blockIdx.x * blockDim.x + threadIdx.x;
    if (i < e) {
        atomicAdd(&g_outdeg[src[i]], 1);
        atomicAdd(&g_indeg[dst[i]], 1);
    }
}

// single-block exclusive scan of in_deg -> rowptr (and cursor copy)
__global__ void scan_kernel(int n) {
    __shared__ int wsum[32];
    __shared__ int s_off;
    int tid = threadIdx.x;
    if (tid == 0) s_off = 0;
    __syncthreads();
    int nIter = (n + 1023) / 1024;
    for (int it = 0; it < nIter; it++) {
        int i = it * 1024 + tid;
        int v = (i < n) ? g_indeg[i] : 0;
        int x = v;
        #pragma unroll
        for (int d = 1; d < 32; d <<= 1) {
            int y = __shfl_up_sync(0xffffffffu, x, d);
            if ((tid & 31) >= d) x += y;
        }
        if ((tid & 31) == 31) wsum[tid >> 5] = x;
        __syncthreads();
        if (tid < 32) {
            int w = wsum[tid];
            #pragma unroll
            for (int d = 1; d < 32; d <<= 1) {
                int y = __shfl_up_sync(0xffffffffu, w, d);
                if (tid >= d) w += y;
            }
            wsum[tid] = w;  // inclusive scan of warp sums
        }
        __syncthreads();
        int base = s_off;
        int warpoff = (tid >= 32) ? wsum[(tid >> 5) - 1] : 0;
        int excl = base + warpoff + x - v;
        if (i < n) { g_rowptr[i] = excl; g_cursor[i] = excl; }
        int total = wsum[31];
        __syncthreads();
        if (tid == 0) s_off = base + total;
        __syncthreads();
    }
    if (tid == 0) g_rowptr[n] = s_off;
}

__global__ void norm_kernel(int n) {
    int i = blockIdx.x * blockDim.x + threadIdx.x;
    if (i < n) {
        g_nd[i] = rsqrtf(fmaxf((float)g_indeg[i], 1.0f));
        g_ns[i] = rsqrtf(fmaxf((float)g_outdeg[i], 1.0f));
    }
}

__global__ void csr_kernel(const int* __restrict__ src, const int* __restrict__ dst, int e) {
    int i = blockIdx.x * blockDim.x + threadIdx.x;
    if (i < e) {
        int d = dst[i];
        int pos = atomicAdd(&g_cursor[d], 1);
        g_srcsorted[pos] = src[i];
    }
}

// ---------------- packed-f32x2 GEMM ----------------
// Tile: 128 rows x (64*NMAT) cols, 256 threads, each thread 8 rows x 4*NMAT cols.
// A rows are DUPLICATED in shared so packed (a,a) operands come free from LDS.128.
// B pairs come free from consecutive columns. Inner loop: pure fma.rn.f32x2.
//   C0 <- A @ B0   epilogue mode0: 0 = store ns[row]*val, 1 = store val (+old if beta0)
//   C1 <- A @ B1   (only if NMAT==2), same mode semantics with mode1/beta1
template <int K, int NMAT>
__global__ void __launch_bounds__(256, 2) gemm_pk(
    const float* __restrict__ A, int lda,
    const float* __restrict__ B0, const float* __restrict__ B1,
    float* __restrict__ C0, float* __restrict__ C1,
    int mode0, int beta0, int mode1, int beta1, int n)
{
    constexpr int KC = 16;
    constexpr int ASTRIDE = 2 * 128 + 4;           // duplicated row, 16B-aligned stride
    constexpr int BSTRIDE = NMAT * 64 + 4;
    __shared__ float Ad[KC][ASTRIDE];
    __shared__ float Bs[KC][BSTRIDE];

    const int tid = threadIdx.x;
    const int tr = tid >> 4;    // 0..15 -> rows tr*8 .. tr*8+7
    const int tc = tid & 15;    // 0..15 -> cols 4*tc..4*tc+3 in each matrix
    const int row0 = blockIdx.x * 128;

    unsigned long long acc[8][2 * NMAT];
    #pragma unroll
    for (int r = 0; r < 8; r++)
        #pragma unroll
        for (int p = 0; p < 2 * NMAT; p++) acc[r][p] = 0ULL;

    for (int kc = 0; kc < K; kc += KC) {
        // ---- stage A (128 x KC) duplicated: Ad[k][2*row] = Ad[k][2*row+1] = A[row][k]
        #pragma unroll
        for (int i = 0; i < 2; i++) {
            int flat = tid + i * 256;        // float4 id over 128*KC/4 = 512
            int row = flat >> 2;             // 4 float4s per row (KC=16)
            int k4 = flat & 3;
            float4 v = make_float4(0.f, 0.f, 0.f, 0.f);
            int gr = row0 + row;
            if (gr < n) v = *(const float4*)(A + (size_t)gr * lda + kc + k4 * 4);
            *(float2*)&Ad[k4 * 4 + 0][2 * row] = make_float2(v.x, v.x);
            *(float2*)&Ad[k4 * 4 + 1][2 * row] = make_float2(v.y, v.y);
            *(float2*)&Ad[k4 * 4 + 2][2 * row] = make_float2(v.z, v.z);
            *(float2*)&Ad[k4 * 4 + 3][2 * row] = make_float2(v.w, v.w);
        }
        // ---- stage B (KC x 64 per matrix)
        #pragma unroll
        for (int m = 0; m < NMAT; m++) {
            const float* Bm = (m == 0) ? B0 : B1;
            int k = tid >> 4;                // 256 float4 ids = KC*16
            int c4 = tid & 15;
            *(float4*)&Bs[k][m * 64 + c4 * 4] =
                *(const float4*)(Bm + (size_t)(kc + k) * 64 + c4 * 4);
        }
        __syncthreads();

        #pragma unroll
        for (int k = 0; k < KC; k++) {
            ulonglong2 a01 = *(const ulonglong2*)&Ad[k][16 * tr + 0];
            ulonglong2 a23 = *(const ulonglong2*)&Ad[k][16 * tr + 4];
            ulonglong2 a45 = *(const ulonglong2*)&Ad[k][16 * tr + 8];
            ulonglong2 a67 = *(const ulonglong2*)&Ad[k][16 * tr + 12];
            unsigned long long av[8] = {a01.x, a01.y, a23.x, a23.y,
                                        a45.x, a45.y, a67.x, a67.y};
            ulonglong2 b0 = *(const ulonglong2*)&Bs[k][4 * tc];
            #pragma unroll
            for (int r = 0; r < 8; r++) {
                fma2(acc[r][0], av[r], b0.x);
                fma2(acc[r][1], av[r], b0.y);
            }
            if (NMAT == 2) {
                ulonglong2 b1 = *(const ulonglong2*)&Bs[k][64 + 4 * tc];
                #pragma unroll
                for (int r = 0; r < 8; r++) {
                    fma2(acc[r][2], av[r], b1.x);
                    fma2(acc[r][3], av[r], b1.y);
                }
            }
        }
        __syncthreads();
    }

    // ---- epilogue ----
    #pragma unroll
    for (int r = 0; r < 8; r++) {
        int gr = row0 + tr * 8 + r;
        if (gr >= n) continue;
        {
            float2 p0 = unpk(acc[r][0]);
            float2 p1 = unpk(acc[r][1]);
            float4 v = make_float4(p0.x, p0.y, p1.x, p1.y);
            float* cp = C0 + (size_t)gr * 64 + tc * 4;
            if (mode0 == 0) {
                float s = g_ns[gr];
                v.x *= s; v.y *= s; v.z *= s; v.w *= s;
            } else if (beta0) {
                float4 o = *(const float4*)cp;
                v.x += o.x; v.y += o.y; v.z += o.z; v.w += o.w;
            }
            *(float4*)cp = v;
        }
        if (NMAT == 2) {
            float2 p2 = unpk(acc[r][2]);
            float2 p3 = unpk(acc[r][3]);
            float4 v = make_float4(p2.x, p2.y, p3.x, p3.y);
            float* cp = C1 + (size_t)gr * 64 + tc * 4;
            if (mode1 == 0) {
                float s = g_ns[gr];
                v.x *= s; v.y *= s; v.z *= s; v.w *= s;
            } else if (beta1) {
                float4 o = *(const float4*)cp;
                v.x += o.x; v.y += o.y; v.z += o.z; v.w += o.w;
            }
            *(float4*)cp = v;
        }
    }
}

// ---------------- CSR gather-aggregate (fused pointwise epilogue) ----------------
// mode 0: hout[d] = relu(nd[d] * sum_{s in N(d)} tin[s] + bias)
// mode 1: hout[d] = sum + bias        (final output, bias = bout)
__global__ void __launch_bounds__(256) aggregate_kernel(
    const float* __restrict__ tin, float* __restrict__ hout,
    const float* __restrict__ bias, int mode, int n)
{
    int g = blockIdx.x * 256 + threadIdx.x;
    int node = g >> 4;
    int lane = g & 15;
    if (node >= n) return;
    int beg = g_rowptr[node];
    int end = g_rowptr[node + 1];
    float4 acc = make_float4(0.f, 0.f, 0.f, 0.f);
    for (int e = beg; e < end; e++) {
        int s = __ldg(&g_srcsorted[e]);
        float4 v = *(const float4*)(tin + (size_t)s * 64 + lane * 4);
        acc.x += v.x; acc.y += v.y; acc.z += v.z; acc.w += v.w;
    }
    float4 bb = *(const float4*)(bias + lane * 4);
    float4 o;
    if (mode == 0) {
        float ndv = g_nd[node];
        o.x = fmaxf(fmaf(acc.x, ndv, bb.x), 0.f);
        o.y = fmaxf(fmaf(acc.y, ndv, bb.y), 0.f);
        o.z = fmaxf(fmaf(acc.z, ndv, bb.z), 0.f);
        o.w = fmaxf(fmaf(acc.w, ndv, bb.w), 0.f);
    } else {
        o.x = acc.x + bb.x; o.y = acc.y + bb.y;
        o.z = acc.z + bb.z; o.w = acc.w + bb.w;
    }
    *(float4*)(hout + (size_t)node * 64 + lane * 4) = o;
}

// ---------------- host ----------------
extern "C" void kernel_launch(void* const* d_in, const int* in_sizes, int n_in,
                              void* d_out, int out_size)
{
    const float* feats = (const float*)d_in[0];
    const int*   src   = (const int*)d_in[1];
    const int*   dst   = (const int*)d_in[2];
    const float* W[5];
    const float* b[5];
    for (int i = 0; i < 5; i++) {
        W[i] = (const float*)d_in[3 + 2 * i];
        b[i] = (const float*)d_in[4 + 2 * i];
    }
    const float* Wout = (const float*)d_in[13];
    const float* bout = (const float*)d_in[14];
    float* out = (float*)d_out;

    int n = in_sizes[0] / FIN;   // 100000
    int e = in_sizes[1];         // 1600000

    float *t, *h, *proj;
    cudaGetSymbolAddress((void**)&t, g_t);
    cudaGetSymbolAddress((void**)&h, g_h);
    cudaGetSymbolAddress((void**)&proj, g_proj);

    int nb256 = (n + 255) / 256;
    int eb256 = (e + 255) / 256;
    int gemm_blocks = (n + 127) / 128;
    int agg_blocks = (n * 16 + 255) / 256;

    // graph preprocessing (recomputed every call: deterministic w.r.t. inputs)
    zero_deg_kernel<<<nb256, 256>>>(n);
    count_kernel<<<eb256, 256>>>(src, dst, e);
    scan_kernel<<<1, 1024>>>(n);
    norm_kernel<<<nb256, 256>>>(n);
    csr_kernel<<<eb256, 256>>>(src, dst, e);

    // layer 0: t = ns * (feats @ W0); h = relu(nd * segsum(t) + b0)
    gemm_pk<FIN, 1><<<gemm_blocks, 256>>>(feats, FIN, W[0], nullptr,
                                          t, nullptr, 0, 0, 0, 0, n);
    aggregate_kernel<<<agg_blocks, 256>>>(t, h, b[0], 0, n);

    // layers 1..4 fused: t = ns*(h@W_l)  AND  proj (+)= h @ Wout_block_{l-1}
    for (int l = 1; l < 5; l++) {
        gemm_pk<HID, 2><<<gemm_blocks, 256>>>(h, HID, W[l],
                                              Wout + (size_t)(l - 1) * HID * 64,
                                              t, proj, 0, 0, 1, (l > 1) ? 1 : 0, n);
        aggregate_kernel<<<agg_blocks, 256>>>(t, h, b[l], 0, n);
    }
    // last JK block: proj += h5 @ Wout_block_4
    gemm_pk<HID, 1><<<gemm_blocks, 256>>>(h, HID, Wout + (size_t)4 * HID * 64, nullptr,
                                          proj, nullptr, 1, 1, 0, 0, n);

    // final: out = segsum(proj[src], dst) + bout
    aggregate_kernel<<<agg_blocks, 256>>>(proj, out, bout, 1, n);
}

// round 3
// speedup vs baseline: 1.0253x; 1.0141x over previous
#include <cuda_runtime.h>
#include <cstdint>
#include <cstddef>

#define NNODES 100000
#define NEDGES 1600000
#define FIN 256
#define HID 64

// ---------------- device scratch (no allocations allowed) ----------------
__device__ int   g_indeg[NNODES];
__device__ int   g_outdeg[NNODES];
__device__ int   g_rowptr[NNODES + 1];
__device__ int   g_cursor[NNODES];
__device__ int   g_srcsorted[NEDGES];
__device__ float g_ns[NNODES];   // rsqrt(max(out_deg,1))
__device__ float g_nd[NNODES];   // rsqrt(max(in_deg,1))
__device__ float g_t[(size_t)NNODES * HID];
__device__ float g_h0[(size_t)NNODES * HID];
__device__ float g_h1[(size_t)NNODES * HID];
__device__ float g_h2[(size_t)NNODES * HID];
__device__ float g_proj[(size_t)NNODES * HID];

// ---------------- packed f32x2 helpers ----------------
__device__ __forceinline__ void fma2(unsigned long long& d,
                                     unsigned long long a,
                                     unsigned long long b) {
    asm("fma.rn.f32x2 %0, %1, %2, %0;" : "+l"(d) : "l"(a), "l"(b));
}
__device__ __forceinline__ float2 unpk(unsigned long long v) {
    float2 r;
    asm("mov.b64 {%0, %1}, %2;" : "=f"(r.x), "=f"(r.y) : "l"(v));
    return r;
}

// ---------------- setup kernels ----------------
__global__ void zero_deg_kernel(int n) {
    int i = blockIdx.x * blockDim.x + threadIdx.x;
    if (i < n) { g_indeg[i] = 0; g_outdeg[i] = 0; }
}

__global__ void count_kernel(const int* __restrict__ src, const int* __restrict__ dst, int e) {
    int i = blockIdx.x * blockDim.x + threadIdx.x;
    if (i < e) {
        atomicAdd(&g_outdeg[src[i]], 1);
        atomicAdd(&g_indeg[dst[i]], 1);
    }
}

__global__ void norm_kernel(int n) {
    int i = blockIdx.x * blockDim.x + threadIdx.x;
    if (i < n) {
        g_nd[i] = rsqrtf(fmaxf((float)g_indeg[i], 1.0f));
        g_ns[i] = rsqrtf(fmaxf((float)g_outdeg[i], 1.0f));
    }
}

// single-block exclusive scan of in_deg -> rowptr (and cursor copy)
__global__ void scan_kernel(int n) {
    __shared__ int wsum[32];
    __shared__ int s_off;
    int tid = threadIdx.x;
    if (tid == 0) s_off = 0;
    __syncthreads();
    int nIter = (n + 1023) / 1024;
    for (int it = 0; it < nIter; it++) {
        int i = it * 1024 + tid;
        int v = (i < n) ? g_indeg[i] : 0;
        int x = v;
        #pragma unroll
        for (int d = 1; d < 32; d <<= 1) {
            int y = __shfl_up_sync(0xffffffffu, x, d);
            if ((tid & 31) >= d) x += y;
        }
        if ((tid & 31) == 31) wsum[tid >> 5] = x;
        __syncthreads();
        if (tid < 32) {
            int w = wsum[tid];
            #pragma unroll
            for (int d = 1; d < 32; d <<= 1) {
                int y = __shfl_up_sync(0xffffffffu, w, d);
                if (tid >= d) w += y;
            }
            wsum[tid] = w;
        }
        __syncthreads();
        int base = s_off;
        int warpoff = (tid >= 32) ? wsum[(tid >> 5) - 1] : 0;
        int excl = base + warpoff + x - v;
        if (i < n) { g_rowptr[i] = excl; g_cursor[i] = excl; }
        int total = wsum[31];
        __syncthreads();
        if (tid == 0) s_off = base + total;
        __syncthreads();
    }
    if (tid == 0) g_rowptr[n] = s_off;
}

__global__ void csr_kernel(const int* __restrict__ src, const int* __restrict__ dst, int e) {
    int i = blockIdx.x * blockDim.x + threadIdx.x;
    if (i < e) {
        int d = dst[i];
        int pos = atomicAdd(&g_cursor[d], 1);
        g_srcsorted[pos] = src[i];
    }
}

// ---------------- packed-f32x2 GEMM (single output matrix) ----------------
// C[n x 64] = A[n x K] @ B[K x 64]
// mode 0: C = ns[row] * (A@B)
// mode 1: C = (beta ? C : 0) + A@B
template <int K>
__global__ void __launch_bounds__(256, 2) gemm_pk(
    const float* __restrict__ A, int lda,
    const float* __restrict__ B,
    float* __restrict__ C,
    int mode, int beta, int n)
{
    constexpr int KC = 16;
    constexpr int ASTRIDE = 2 * 128 + 4;   // duplicated row pairs, 16B-friendly stride
    __shared__ float Ad[KC][ASTRIDE];
    __shared__ float Bs[KC][64 + 4];

    const int tid = threadIdx.x;
    const int tr = tid >> 4;    // 0..15 -> rows tr*8 .. tr*8+7
    const int tc = tid & 15;    // 0..15 -> cols 4*tc..4*tc+3
    const int row0 = blockIdx.x * 128;

    unsigned long long acc[8][2];
    #pragma unroll
    for (int r = 0; r < 8; r++) { acc[r][0] = 0ULL; acc[r][1] = 0ULL; }

    for (int kc = 0; kc < K; kc += KC) {
        // stage A (128 x KC) duplicated: Ad[k][2*row] = Ad[k][2*row+1] = A[row][k]
        #pragma unroll
        for (int i = 0; i < 2; i++) {
            int flat = tid + i * 256;        // float4 id over 512
            int row = flat >> 2;
            int k4 = flat & 3;
            float4 v = make_float4(0.f, 0.f, 0.f, 0.f);
            int gr = row0 + row;
            if (gr < n) v = *(const float4*)(A + (size_t)gr * lda + kc + k4 * 4);
            *(float2*)&Ad[k4 * 4 + 0][2 * row] = make_float2(v.x, v.x);
            *(float2*)&Ad[k4 * 4 + 1][2 * row] = make_float2(v.y, v.y);
            *(float2*)&Ad[k4 * 4 + 2][2 * row] = make_float2(v.z, v.z);
            *(float2*)&Ad[k4 * 4 + 3][2 * row] = make_float2(v.w, v.w);
        }
        // stage B (KC x 64)
        {
            int k = tid >> 4;
            int c4 = tid & 15;
            *(float4*)&Bs[k][c4 * 4] = *(const float4*)(B + (size_t)(kc + k) * 64 + c4 * 4);
        }
        __syncthreads();

        #pragma unroll
        for (int k = 0; k < KC; k++) {
            ulonglong2 a01 = *(const ulonglong2*)&Ad[k][16 * tr + 0];
            ulonglong2 a23 = *(const ulonglong2*)&Ad[k][16 * tr + 4];
            ulonglong2 a45 = *(const ulonglong2*)&Ad[k][16 * tr + 8];
            ulonglong2 a67 = *(const ulonglong2*)&Ad[k][16 * tr + 12];
            unsigned long long av[8] = {a01.x, a01.y, a23.x, a23.y,
                                        a45.x, a45.y, a67.x, a67.y};
            ulonglong2 b0 = *(const ulonglong2*)&Bs[k][4 * tc];
            #pragma unroll
            for (int r = 0; r < 8; r++) {
                fma2(acc[r][0], av[r], b0.x);
                fma2(acc[r][1], av[r], b0.y);
            }
        }
        __syncthreads();
    }

    #pragma unroll
    for (int r = 0; r < 8; r++) {
        int gr = row0 + tr * 8 + r;
        if (gr >= n) continue;
        float2 p0 = unpk(acc[r][0]);
        float2 p1 = unpk(acc[r][1]);
        float4 v = make_float4(p0.x, p0.y, p1.x, p1.y);
        float* cp = C + (size_t)gr * 64 + tc * 4;
        if (mode == 0) {
            float s = g_ns[gr];
            v.x *= s; v.y *= s; v.z *= s; v.w *= s;
        } else if (beta) {
            float4 o = *(const float4*)cp;
            v.x += o.x; v.y += o.y; v.z += o.z; v.w += o.w;
        }
        *(float4*)cp = v;
    }
}

// ---------------- CSR gather-aggregate (fused pointwise epilogue) ----------------
// NS:    multiply each gathered message by ns[src] (used only for layer 0)
// RELU:  hout[d] = relu(nd[d]*sum + bias); else hout[d] = sum + bias
template <bool NS, bool RELU>
__global__ void __launch_bounds__(256) aggregate_kernel(
    const float* __restrict__ tin, float* __restrict__ hout,
    const float* __restrict__ bias, int n)
{
    int g = blockIdx.x * 256 + threadIdx.x;
    int node = g >> 4;
    int lane = g & 15;
    if (node >= n) return;
    int beg = g_rowptr[node];
    int end = g_rowptr[node + 1];
    float4 acc = make_float4(0.f, 0.f, 0.f, 0.f);

    int e = beg;
    for (; e + 4 <= end; e += 4) {
        int s0 = __ldg(&g_srcsorted[e + 0]);
        int s1 = __ldg(&g_srcsorted[e + 1]);
        int s2 = __ldg(&g_srcsorted[e + 2]);
        int s3 = __ldg(&g_srcsorted[e + 3]);
        float4 v0 = *(const float4*)(tin + (size_t)s0 * 64 + lane * 4);
        float4 v1 = *(const float4*)(tin + (size_t)s1 * 64 + lane * 4);
        float4 v2 = *(const float4*)(tin + (size_t)s2 * 64 + lane * 4);
        float4 v3 = *(const float4*)(tin + (size_t)s3 * 64 + lane * 4);
        if (NS) {
            float w0 = __ldg(&g_ns[s0]);
            float w1 = __ldg(&g_ns[s1]);
            float w2 = __ldg(&g_ns[s2]);
            float w3 = __ldg(&g_ns[s3]);
            acc.x = fmaf(v0.x, w0, acc.x); acc.y = fmaf(v0.y, w0, acc.y);
            acc.z = fmaf(v0.z, w0, acc.z); acc.w = fmaf(v0.w, w0, acc.w);
            acc.x = fmaf(v1.x, w1, acc.x); acc.y = fmaf(v1.y, w1, acc.y);
            acc.z = fmaf(v1.z, w1, acc.z); acc.w = fmaf(v1.w, w1, acc.w);
            acc.x = fmaf(v2.x, w2, acc.x); acc.y = fmaf(v2.y, w2, acc.y);
            acc.z = fmaf(v2.z, w2, acc.z); acc.w = fmaf(v2.w, w2, acc.w);
            acc.x = fmaf(v3.x, w3, acc.x); acc.y = fmaf(v3.y, w3, acc.y);
            acc.z = fmaf(v3.z, w3, acc.z); acc.w = fmaf(v3.w, w3, acc.w);
        } else {
            acc.x += v0.x + v1.x + v2.x + v3.x;
            acc.y += v0.y + v1.y + v2.y + v3.y;
            acc.z += v0.z + v1.z + v2.z + v3.z;
            acc.w += v0.w + v1.w + v2.w + v3.w;
        }
    }
    for (; e < end; e++) {
        int s = __ldg(&g_srcsorted[e]);
        float4 v = *(const float4*)(tin + (size_t)s * 64 + lane * 4);
        float w = NS ? __ldg(&g_ns[s]) : 1.0f;
        if (NS) {
            acc.x = fmaf(v.x, w, acc.x); acc.y = fmaf(v.y, w, acc.y);
            acc.z = fmaf(v.z, w, acc.z); acc.w = fmaf(v.w, w, acc.w);
        } else {
            acc.x += v.x; acc.y += v.y; acc.z += v.z; acc.w += v.w;
        }
    }

    float4 bb = *(const float4*)(bias + lane * 4);
    float4 o;
    if (RELU) {
        float ndv = g_nd[node];
        o.x = fmaxf(fmaf(acc.x, ndv, bb.x), 0.f);
        o.y = fmaxf(fmaf(acc.y, ndv, bb.y), 0.f);
        o.z = fmaxf(fmaf(acc.z, ndv, bb.z), 0.f);
        o.w = fmaxf(fmaf(acc.w, ndv, bb.w), 0.f);
    } else {
        o.x = acc.x + bb.x; o.y = acc.y + bb.y;
        o.z = acc.z + bb.z; o.w = acc.w + bb.w;
    }
    *(float4*)(hout + (size_t)node * 64 + lane * 4) = o;
}

// ---------------- host ----------------
extern "C" void kernel_launch(void* const* d_in, const int* in_sizes, int n_in,
                              void* d_out, int out_size)
{
    const float* feats = (const float*)d_in[0];
    const int*   src   = (const int*)d_in[1];
    const int*   dst   = (const int*)d_in[2];
    const float* W[5];
    const float* b[5];
    for (int i = 0; i < 5; i++) {
        W[i] = (const float*)d_in[3 + 2 * i];
        b[i] = (const float*)d_in[4 + 2 * i];
    }
    const float* Wout = (const float*)d_in[13];
    const float* bout = (const float*)d_in[14];
    float* out = (float*)d_out;

    int n = in_sizes[0] / FIN;   // 100000
    int e = in_sizes[1];         // 1600000

    float *t, *proj, *hb[3];
    cudaGetSymbolAddress((void**)&t, g_t);
    cudaGetSymbolAddress((void**)&proj, g_proj);
    cudaGetSymbolAddress((void**)&hb[0], g_h0);
    cudaGetSymbolAddress((void**)&hb[1], g_h1);
    cudaGetSymbolAddress((void**)&hb[2], g_h2);

    // one-time host resources (streams/events are not device memory)
    static cudaStream_t side = nullptr;
    static cudaEvent_t evFork, evPre, evH[6], evP[5];
    if (!side) {
        cudaStreamCreateWithFlags(&side, cudaStreamNonBlocking);
        cudaEventCreateWithFlags(&evFork, cudaEventDisableTiming);
        cudaEventCreateWithFlags(&evPre, cudaEventDisableTiming);
        for (int i = 0; i < 6; i++) cudaEventCreateWithFlags(&evH[i], cudaEventDisableTiming);
        for (int i = 0; i < 5; i++) cudaEventCreateWithFlags(&evP[i], cudaEventDisableTiming);
    }

    int nb256 = (n + 255) / 256;
    int eb256 = (e + 255) / 256;
    int gemm_blocks = (n + 127) / 128;
    int agg_blocks = (n * 16 + 255) / 256;

    // ---- fork: preprocessing on side stream, GEMM L0 on main ----
    cudaEventRecord(evFork, 0);
    cudaStreamWaitEvent(side, evFork, 0);

    zero_deg_kernel<<<nb256, 256, 0, side>>>(n);
    count_kernel<<<eb256, 256, 0, side>>>(src, dst, e);
    norm_kernel<<<nb256, 256, 0, side>>>(n);
    scan_kernel<<<1, 1024, 0, side>>>(n);
    csr_kernel<<<eb256, 256, 0, side>>>(src, dst, e);
    cudaEventRecord(evPre, side);

    // main: t = feats @ W0 (plain; norm_src applied per-edge in agg L0)
    gemm_pk<FIN><<<gemm_blocks, 256>>>(feats, FIN, W[0], t, 1, 0, n);

    // join, then layer-0 aggregate: h1 = relu(nd * sum(ns[s]*t[s]) + b0)
    cudaStreamWaitEvent(0, evPre, 0);
    aggregate_kernel<true, true><<<agg_blocks, 256>>>(t, hb[0], b[0], n);
    cudaEventRecord(evH[1], 0);

    // layers 1..4
    for (int l = 1; l < 5; l++) {
        float* h_in = hb[(l - 1) % 3];
        float* h_out = hb[l % 3];

        // side: proj (+)= h_in @ Wout_{l-1}   (off critical path)
        cudaStreamWaitEvent(side, evH[l], 0);
        gemm_pk<HID><<<gemm_blocks, 256, 0, side>>>(
            h_in, HID, Wout + (size_t)(l - 1) * HID * 64, proj, 1, (l > 1) ? 1 : 0, n);
        cudaEventRecord(evP[l - 1], side);

        // main: t = ns * (h_in @ W_l)
        gemm_pk<HID><<<gemm_blocks, 256>>>(h_in, HID, W[l], t, 0, 0, n);
        // buffer-reuse guard: h_out was read by proj gemm (l-3)
        if (l >= 3) cudaStreamWaitEvent(0, evP[l - 3], 0);
        aggregate_kernel<false, true><<<agg_blocks, 256>>>(t, h_out, b[l], n);
        cudaEventRecord(evH[l + 1], 0);
    }

    // side: proj += h5 @ Wout_4
    float* h5 = hb[4 % 3];
    cudaStreamWaitEvent(side, evH[5], 0);
    gemm_pk<HID><<<gemm_blocks, 256, 0, side>>>(
        h5, HID, Wout + (size_t)4 * HID * 64, proj, 1, 1, n);
    cudaEventRecord(evP[4], side);

    // main: out = sum(proj[src]) + bout
    cudaStreamWaitEvent(0, evP[4], 0);
    aggregate_kernel<false, false><<<agg_blocks, 256>>>(proj, out, bout, n);
}

// round 4
// speedup vs baseline: 1.1166x; 1.0890x over previous
#include <cuda_runtime.h>
#include <cstdint>
#include <cstddef>

#define NNODES 100000
#define NEDGES 1600000
#define FIN 256
#define HID 64
#define CHUNK 4096
#define NCHUNK ((NNODES + CHUNK - 1) / CHUNK)

// ---------------- device scratch (no allocations allowed) ----------------
__device__ int   g_indeg[NNODES];
__device__ int   g_outdeg[NNODES];
__device__ int   g_rowptr[NNODES + 1];
__device__ int   g_cursor[NNODES];
__device__ int   g_srcsorted[NEDGES];
__device__ int   g_chunksum[NCHUNK];
__device__ int   g_chunkoff[NCHUNK];
__device__ float g_ns[NNODES];   // rsqrt(max(out_deg,1))
__device__ float g_nd[NNODES];   // rsqrt(max(in_deg,1))
__device__ float g_t[(size_t)NNODES * HID];
__device__ float g_h0[(size_t)NNODES * HID];
__device__ float g_h1[(size_t)NNODES * HID];
__device__ float g_h2[(size_t)NNODES * HID];
__device__ float g_proj[(size_t)NNODES * HID];

// ---------------- packed f32x2 helpers ----------------
__device__ __forceinline__ void fma2(unsigned long long& d,
                                     unsigned long long a,
                                     unsigned long long b) {
    asm("fma.rn.f32x2 %0, %1, %2, %0;" : "+l"(d) : "l"(a), "l"(b));
}
__device__ __forceinline__ float2 unpk(unsigned long long v) {
    float2 r;
    asm("mov.b64 {%0, %1}, %2;" : "=f"(r.x), "=f"(r.y) : "l"(v));
    return r;
}

// ---------------- setup kernels ----------------
__global__ void zero_deg_kernel(int n) {
    int i = blockIdx.x * blockDim.x + threadIdx.x;
    if (i < n) { g_indeg[i] = 0; g_outdeg[i] = 0; }
}

__global__ void count_kernel(const int* __restrict__ src, const int* __restrict__ dst, int e) {
    int i = blockIdx.x * blockDim.x + threadIdx.x;
    if (i < e) {
        atomicAdd(&g_outdeg[src[i]], 1);
        atomicAdd(&g_indeg[dst[i]], 1);
    }
}

// phase 1: per-chunk sums of indeg (grid = NCHUNK, 1024 threads, 4 elems/thread)
__global__ void __launch_bounds__(1024) chunksum_kernel(int n) {
    __shared__ int wsum[32];
    int tid = threadIdx.x;
    int base = blockIdx.x * CHUNK + tid * 4;
    int s = 0;
    #pragma unroll
    for (int j = 0; j < 4; j++) {
        int i = base + j;
        if (i < n) s += g_indeg[i];
    }
    #pragma unroll
    for (int d = 16; d > 0; d >>= 1) s += __shfl_down_sync(0xffffffffu, s, d);
    if ((tid & 31) == 0) wsum[tid >> 5] = s;
    __syncthreads();
    if (tid < 32) {
        int v = wsum[tid];
        #pragma unroll
        for (int d = 16; d > 0; d >>= 1) v += __shfl_down_sync(0xffffffffu, v, d);
        if (tid == 0) g_chunksum[blockIdx.x] = v;
    }
}

// phase 2: 1-warp exclusive scan of chunk sums (NCHUNK <= 32)
__global__ void chunkscan_kernel(int n) {
    int tid = threadIdx.x;
    int v = (tid < NCHUNK) ? g_chunksum[tid] : 0;
    int x = v;
    #pragma unroll
    for (int d = 1; d < 32; d <<= 1) {
        int y = __shfl_up_sync(0xffffffffu, x, d);
        if (tid >= d) x += y;
    }
    if (tid < NCHUNK) g_chunkoff[tid] = x - v;   // exclusive
    if (tid == 31) g_rowptr[n] = x;              // total = inclusive of last lane
}

// phase 3: per-chunk rescan -> rowptr/cursor; fused norm computation
__global__ void __launch_bounds__(1024) rescan_kernel(int n) {
    __shared__ int wsum[32];
    int tid = threadIdx.x;
    int base = blockIdx.x * CHUNK + tid * 4;

    int v[4];
    int s = 0;
    #pragma unroll
    for (int j = 0; j < 4; j++) {
        int i = base + j;
        v[j] = (i < n) ? g_indeg[i] : 0;
        s += v[j];
    }
    // warp inclusive scan of thread sums
    int x = s;
    #pragma unroll
    for (int d = 1; d < 32; d <<= 1) {
        int y = __shfl_up_sync(0xffffffffu, x, d);
        if ((tid & 31) >= d) x += y;
    }
    if ((tid & 31) == 31) wsum[tid >> 5] = x;
    __syncthreads();
    if (tid < 32) {
        int w = wsum[tid];
        #pragma unroll
        for (int d = 1; d < 32; d <<= 1) {
            int y = __shfl_up_sync(0xffffffffu, w, d);
            if (tid >= d) w += y;
        }
        wsum[tid] = w;   // inclusive warp sums
    }
    __syncthreads();
    int warpoff = (tid >= 32) ? wsum[(tid >> 5) - 1] : 0;
    int excl = g_chunkoff[blockIdx.x] + warpoff + (x - s);

    #pragma unroll
    for (int j = 0; j < 4; j++) {
        int i = base + j;
        if (i < n) {
            g_rowptr[i] = excl;
            g_cursor[i] = excl;
            g_nd[i] = rsqrtf(fmaxf((float)v[j], 1.0f));
            g_ns[i] = rsqrtf(fmaxf((float)g_outdeg[i], 1.0f));
        }
        excl += v[j];
    }
}

__global__ void csr_kernel(const int* __restrict__ src, const int* __restrict__ dst, int e) {
    int i = blockIdx.x * blockDim.x + threadIdx.x;
    if (i < e) {
        int d = dst[i];
        int pos = atomicAdd(&g_cursor[d], 1);
        g_srcsorted[pos] = src[i];
    }
}

// ---------------- packed-f32x2 GEMM (single output matrix) ----------------
// C[n x 64] = A[n x K] @ B[K x 64]
// mode 0: C = ns[row] * (A@B)
// mode 1: C = (beta ? C : 0) + A@B
template <int K>
__global__ void __launch_bounds__(256, 2) gemm_pk(
    const float* __restrict__ A, int lda,
    const float* __restrict__ B,
    float* __restrict__ C,
    int mode, int beta, int n)
{
    constexpr int KC = 16;
    constexpr int ASTRIDE = 2 * 128 + 4;
    __shared__ float Ad[KC][ASTRIDE];
    __shared__ float Bs[KC][64 + 4];

    const int tid = threadIdx.x;
    const int tr = tid >> 4;
    const int tc = tid & 15;
    const int row0 = blockIdx.x * 128;

    unsigned long long acc[8][2];
    #pragma unroll
    for (int r = 0; r < 8; r++) { acc[r][0] = 0ULL; acc[r][1] = 0ULL; }

    for (int kc = 0; kc < K; kc += KC) {
        #pragma unroll
        for (int i = 0; i < 2; i++) {
            int flat = tid + i * 256;
            int row = flat >> 2;
            int k4 = flat & 3;
            float4 v = make_float4(0.f, 0.f, 0.f, 0.f);
            int gr = row0 + row;
            if (gr < n) v = *(const float4*)(A + (size_t)gr * lda + kc + k4 * 4);
            *(float2*)&Ad[k4 * 4 + 0][2 * row] = make_float2(v.x, v.x);
            *(float2*)&Ad[k4 * 4 + 1][2 * row] = make_float2(v.y, v.y);
            *(float2*)&Ad[k4 * 4 + 2][2 * row] = make_float2(v.z, v.z);
            *(float2*)&Ad[k4 * 4 + 3][2 * row] = make_float2(v.w, v.w);
        }
        {
            int k = tid >> 4;
            int c4 = tid & 15;
            *(float4*)&Bs[k][c4 * 4] = *(const float4*)(B + (size_t)(kc + k) * 64 + c4 * 4);
        }
        __syncthreads();

        #pragma unroll
        for (int k = 0; k < KC; k++) {
            ulonglong2 a01 = *(const ulonglong2*)&Ad[k][16 * tr + 0];
            ulonglong2 a23 = *(const ulonglong2*)&Ad[k][16 * tr + 4];
            ulonglong2 a45 = *(const ulonglong2*)&Ad[k][16 * tr + 8];
            ulonglong2 a67 = *(const ulonglong2*)&Ad[k][16 * tr + 12];
            unsigned long long av[8] = {a01.x, a01.y, a23.x, a23.y,
                                        a45.x, a45.y, a67.x, a67.y};
            ulonglong2 b0 = *(const ulonglong2*)&Bs[k][4 * tc];
            #pragma unroll
            for (int r = 0; r < 8; r++) {
                fma2(acc[r][0], av[r], b0.x);
                fma2(acc[r][1], av[r], b0.y);
            }
        }
        __syncthreads();
    }

    #pragma unroll
    for (int r = 0; r < 8; r++) {
        int gr = row0 + tr * 8 + r;
        if (gr >= n) continue;
        float2 p0 = unpk(acc[r][0]);
        float2 p1 = unpk(acc[r][1]);
        float4 v = make_float4(p0.x, p0.y, p1.x, p1.y);
        float* cp = C + (size_t)gr * 64 + tc * 4;
        if (mode == 0) {
            float s = g_ns[gr];
            v.x *= s; v.y *= s; v.z *= s; v.w *= s;
        } else if (beta) {
            float4 o = *(const float4*)cp;
            v.x += o.x; v.y += o.y; v.z += o.z; v.w += o.w;
        }
        *(float4*)cp = v;
    }
}

// ---------------- CSR gather-aggregate (fused pointwise epilogue) ----------------
template <bool NS, bool RELU>
__global__ void __launch_bounds__(256) aggregate_kernel(
    const float* __restrict__ tin, float* __restrict__ hout,
    const float* __restrict__ bias, int n)
{
    int g = blockIdx.x * 256 + threadIdx.x;
    int node = g >> 4;
    int lane = g & 15;
    if (node >= n) return;
    int beg = g_rowptr[node];
    int end = g_rowptr[node + 1];
    float4 acc = make_float4(0.f, 0.f, 0.f, 0.f);

    int e = beg;
    for (; e + 4 <= end; e += 4) {
        int s0 = __ldg(&g_srcsorted[e + 0]);
        int s1 = __ldg(&g_srcsorted[e + 1]);
        int s2 = __ldg(&g_srcsorted[e + 2]);
        int s3 = __ldg(&g_srcsorted[e + 3]);
        float4 v0 = *(const float4*)(tin + (size_t)s0 * 64 + lane * 4);
        float4 v1 = *(const float4*)(tin + (size_t)s1 * 64 + lane * 4);
        float4 v2 = *(const float4*)(tin + (size_t)s2 * 64 + lane * 4);
        float4 v3 = *(const float4*)(tin + (size_t)s3 * 64 + lane * 4);
        if (NS) {
            float w0 = __ldg(&g_ns[s0]);
            float w1 = __ldg(&g_ns[s1]);
            float w2 = __ldg(&g_ns[s2]);
            float w3 = __ldg(&g_ns[s3]);
            acc.x = fmaf(v0.x, w0, acc.x); acc.y = fmaf(v0.y, w0, acc.y);
            acc.z = fmaf(v0.z, w0, acc.z); acc.w = fmaf(v0.w, w0, acc.w);
            acc.x = fmaf(v1.x, w1, acc.x); acc.y = fmaf(v1.y, w1, acc.y);
            acc.z = fmaf(v1.z, w1, acc.z); acc.w = fmaf(v1.w, w1, acc.w);
            acc.x = fmaf(v2.x, w2, acc.x); acc.y = fmaf(v2.y, w2, acc.y);
            acc.z = fmaf(v2.z, w2, acc.z); acc.w = fmaf(v2.w, w2, acc.w);
            acc.x = fmaf(v3.x, w3, acc.x); acc.y = fmaf(v3.y, w3, acc.y);
            acc.z = fmaf(v3.z, w3, acc.z); acc.w = fmaf(v3.w, w3, acc.w);
        } else {
            acc.x += v0.x + v1.x + v2.x + v3.x;
            acc.y += v0.y + v1.y + v2.y + v3.y;
            acc.z += v0.z + v1.z + v2.z + v3.z;
            acc.w += v0.w + v1.w + v2.w + v3.w;
        }
    }
    for (; e < end; e++) {
        int s = __ldg(&g_srcsorted[e]);
        float4 v = *(const float4*)(tin + (size_t)s * 64 + lane * 4);
        if (NS) {
            float w = __ldg(&g_ns[s]);
            acc.x = fmaf(v.x, w, acc.x); acc.y = fmaf(v.y, w, acc.y);
            acc.z = fmaf(v.z, w, acc.z); acc.w = fmaf(v.w, w, acc.w);
        } else {
            acc.x += v.x; acc.y += v.y; acc.z += v.z; acc.w += v.w;
        }
    }

    float4 bb = *(const float4*)(bias + lane * 4);
    float4 o;
    if (RELU) {
        float ndv = g_nd[node];
        o.x = fmaxf(fmaf(acc.x, ndv, bb.x), 0.f);
        o.y = fmaxf(fmaf(acc.y, ndv, bb.y), 0.f);
        o.z = fmaxf(fmaf(acc.z, ndv, bb.z), 0.f);
        o.w = fmaxf(fmaf(acc.w, ndv, bb.w), 0.f);
    } else {
        o.x = acc.x + bb.x; o.y = acc.y + bb.y;
        o.z = acc.z + bb.z; o.w = acc.w + bb.w;
    }
    *(float4*)(hout + (size_t)node * 64 + lane * 4) = o;
}

// ---------------- host ----------------
extern "C" void kernel_launch(void* const* d_in, const int* in_sizes, int n_in,
                              void* d_out, int out_size)
{
    const float* feats = (const float*)d_in[0];
    const int*   src   = (const int*)d_in[1];
    const int*   dst   = (const int*)d_in[2];
    const float* W[5];
    const float* b[5];
    for (int i = 0; i < 5; i++) {
        W[i] = (const float*)d_in[3 + 2 * i];
        b[i] = (const float*)d_in[4 + 2 * i];
    }
    const float* Wout = (const float*)d_in[13];
    const float* bout = (const float*)d_in[14];
    float* out = (float*)d_out;

    int n = in_sizes[0] / FIN;   // 100000
    int e = in_sizes[1];         // 1600000

    float *t, *proj, *hb[3];
    cudaGetSymbolAddress((void**)&t, g_t);
    cudaGetSymbolAddress((void**)&proj, g_proj);
    cudaGetSymbolAddress((void**)&hb[0], g_h0);
    cudaGetSymbolAddress((void**)&hb[1], g_h1);
    cudaGetSymbolAddress((void**)&hb[2], g_h2);

    static cudaStream_t side = nullptr;
    static cudaEvent_t evFork, evPre, evH[6], evP[5];
    if (!side) {
        cudaStreamCreateWithFlags(&side, cudaStreamNonBlocking);
        cudaEventCreateWithFlags(&evFork, cudaEventDisableTiming);
        cudaEventCreateWithFlags(&evPre, cudaEventDisableTiming);
        for (int i = 0; i < 6; i++) cudaEventCreateWithFlags(&evH[i], cudaEventDisableTiming);
        for (int i = 0; i < 5; i++) cudaEventCreateWithFlags(&evP[i], cudaEventDisableTiming);
    }

    int nb256 = (n + 255) / 256;
    int eb256 = (e + 255) / 256;
    int gemm_blocks = (n + 127) / 128;
    int agg_blocks = (n * 16 + 255) / 256;
    int nchunk = (n + CHUNK - 1) / CHUNK;

    // ---- fork: preprocessing on side stream, GEMM L0 on main ----
    cudaEventRecord(evFork, 0);
    cudaStreamWaitEvent(side, evFork, 0);

    zero_deg_kernel<<<nb256, 256, 0, side>>>(n);
    count_kernel<<<eb256, 256, 0, side>>>(src, dst, e);
    chunksum_kernel<<<nchunk, 1024, 0, side>>>(n);
    chunkscan_kernel<<<1, 32, 0, side>>>(n);
    rescan_kernel<<<nchunk, 1024, 0, side>>>(n);   // writes rowptr/cursor + ns/nd
    csr_kernel<<<eb256, 256, 0, side>>>(src, dst, e);
    cudaEventRecord(evPre, side);

    // main: t = feats @ W0 (plain; norm_src applied per-edge in agg L0)
    gemm_pk<FIN><<<gemm_blocks, 256>>>(feats, FIN, W[0], t, 1, 0, n);

    // join, then layer-0 aggregate: h = relu(nd * sum(ns[s]*t[s]) + b0)
    cudaStreamWaitEvent(0, evPre, 0);
    aggregate_kernel<true, true><<<agg_blocks, 256>>>(t, hb[0], b[0], n);
    cudaEventRecord(evH[1], 0);

    // layers 1..4
    for (int l = 1; l < 5; l++) {
        float* h_in = hb[(l - 1) % 3];
        float* h_out = hb[l % 3];

        cudaStreamWaitEvent(side, evH[l], 0);
        gemm_pk<HID><<<gemm_blocks, 256, 0, side>>>(
            h_in, HID, Wout + (size_t)(l - 1) * HID * 64, proj, 1, (l > 1) ? 1 : 0, n);
        cudaEventRecord(evP[l - 1], side);

        gemm_pk<HID><<<gemm_blocks, 256>>>(h_in, HID, W[l], t, 0, 0, n);
        if (l >= 3) cudaStreamWaitEvent(0, evP[l - 3], 0);
        aggregate_kernel<false, true><<<agg_blocks, 256>>>(t, h_out, b[l], n);
        cudaEventRecord(evH[l + 1], 0);
    }

    // side: proj += h5 @ Wout_4
    float* h5 = hb[4 % 3];
    cudaStreamWaitEvent(side, evH[5], 0);
    gemm_pk<HID><<<gemm_blocks, 256, 0, side>>>(
        h5, HID, Wout + (size_t)4 * HID * 64, proj, 1, 1, n);
    cudaEventRecord(evP[4], side);

    // main: out = sum(proj[src]) + bout
    cudaStreamWaitEvent(0, evP[4], 0);
    aggregate_kernel<false, false><<<agg_blocks, 256>>>(proj, out, bout, n);
}

// round 5
// speedup vs baseline: 1.3018x; 1.1659x over previous
#include <cuda_runtime.h>
#include <cstdint>
#include <cstddef>

#define NNODES 100000
#define NEDGES 1600000
#define FIN 256
#define HID 64
#define CHUNK 4096
#define NCHUNK ((NNODES + CHUNK - 1) / CHUNK)

// ---------------- device scratch (no allocations allowed) ----------------
__device__ int   g_indeg[NNODES];
__device__ int   g_outdeg[NNODES];
__device__ int   g_rowptr[NNODES + 1];
__device__ int   g_cursor[NNODES];
__device__ int   g_srcsorted[NEDGES];
__device__ int   g_chunksum[NCHUNK];
__device__ float g_ns[NNODES];   // rsqrt(max(out_deg,1))
__device__ float g_nd[NNODES];   // rsqrt(max(in_deg,1))
__device__ float g_t[(size_t)NNODES * HID];
__device__ float g_h0[(size_t)NNODES * HID];
__device__ float g_h1[(size_t)NNODES * HID];
__device__ float g_h2[(size_t)NNODES * HID];
__device__ float g_proj[(size_t)NNODES * HID];

// ---------------- packed f32x2 helpers ----------------
__device__ __forceinline__ void fma2(unsigned long long& d,
                                     unsigned long long a,
                                     unsigned long long b) {
    asm("fma.rn.f32x2 %0, %1, %2, %0;" : "+l"(d) : "l"(a), "l"(b));
}
__device__ __forceinline__ unsigned long long dup2(float b) {
    unsigned long long r;
    asm("mov.b64 %0, {%1, %1};" : "=l"(r) : "f"(b));
    return r;
}
__device__ __forceinline__ float2 unpk(unsigned long long v) {
    float2 r;
    asm("mov.b64 {%0, %1}, %2;" : "=f"(r.x), "=f"(r.y) : "l"(v));
    return r;
}

// ---------------- setup kernels ----------------
__global__ void zero_in_kernel(int n) {
    int i = blockIdx.x * blockDim.x + threadIdx.x;
    if (i < n) g_indeg[i] = 0;
}
__global__ void zero_out_kernel(int n) {
    int i = blockIdx.x * blockDim.x + threadIdx.x;
    if (i < n) g_outdeg[i] = 0;
}

__global__ void count_in_kernel(const int* __restrict__ dst, int e) {
    int i4 = (blockIdx.x * blockDim.x + threadIdx.x) * 4;
    if (i4 + 3 < e) {
        int4 d = *(const int4*)(dst + i4);
        atomicAdd(&g_indeg[d.x], 1);
        atomicAdd(&g_indeg[d.y], 1);
        atomicAdd(&g_indeg[d.z], 1);
        atomicAdd(&g_indeg[d.w], 1);
    } else {
        for (int i = i4; i < e; i++) atomicAdd(&g_indeg[dst[i]], 1);
    }
}
__global__ void count_out_kernel(const int* __restrict__ src, int e) {
    int i4 = (blockIdx.x * blockDim.x + threadIdx.x) * 4;
    if (i4 + 3 < e) {
        int4 s = *(const int4*)(src + i4);
        atomicAdd(&g_outdeg[s.x], 1);
        atomicAdd(&g_outdeg[s.y], 1);
        atomicAdd(&g_outdeg[s.z], 1);
        atomicAdd(&g_outdeg[s.w], 1);
    } else {
        for (int i = i4; i < e; i++) atomicAdd(&g_outdeg[src[i]], 1);
    }
}

__global__ void ns_kernel(int n) {
    int i = blockIdx.x * blockDim.x + threadIdx.x;
    if (i < n) g_ns[i] = rsqrtf(fmaxf((float)g_outdeg[i], 1.0f));
}

// phase 1: per-chunk sums of indeg
__global__ void __launch_bounds__(1024) chunksum_kernel(int n) {
    __shared__ int wsum[32];
    int tid = threadIdx.x;
    int base = blockIdx.x * CHUNK + tid * 4;
    int s = 0;
    #pragma unroll
    for (int j = 0; j < 4; j++) {
        int i = base + j;
        if (i < n) s += g_indeg[i];
    }
    #pragma unroll
    for (int d = 16; d > 0; d >>= 1) s += __shfl_down_sync(0xffffffffu, s, d);
    if ((tid & 31) == 0) wsum[tid >> 5] = s;
    __syncthreads();
    if (tid < 32) {
        int v = wsum[tid];
        #pragma unroll
        for (int d = 16; d > 0; d >>= 1) v += __shfl_down_sync(0xffffffffu, v, d);
        if (tid == 0) g_chunksum[blockIdx.x] = v;
    }
}

// phase 2: per-chunk rescan (with inlined chunk-prefix) -> rowptr/cursor + nd
__global__ void __launch_bounds__(1024) rescan_kernel(int n) {
    __shared__ int wsum[32];
    __shared__ int s_chunkoff;
    int tid = threadIdx.x;

    // inline chunk-offset: sum of chunksum[c] for c < blockIdx.x (NCHUNK <= 32)
    if (tid < 32) {
        int v = (tid < NCHUNK) ? g_chunksum[tid] : 0;
        int before = (tid < (int)blockIdx.x) ? v : 0;
        int all = v;
        #pragma unroll
        for (int d = 16; d > 0; d >>= 1) {
            before += __shfl_down_sync(0xffffffffu, before, d);
            all    += __shfl_down_sync(0xffffffffu, all, d);
        }
        if (tid == 0) {
            s_chunkoff = before;
            if (blockIdx.x == 0) g_rowptr[n] = all;
        }
    }

    int base = blockIdx.x * CHUNK + tid * 4;
    int v[4];
    int s = 0;
    #pragma unroll
    for (int j = 0; j < 4; j++) {
        int i = base + j;
        v[j] = (i < n) ? g_indeg[i] : 0;
        s += v[j];
    }
    int x = s;
    #pragma unroll
    for (int d = 1; d < 32; d <<= 1) {
        int y = __shfl_up_sync(0xffffffffu, x, d);
        if ((tid & 31) >= d) x += y;
    }
    if ((tid & 31) == 31) wsum[tid >> 5] = x;
    __syncthreads();
    if (tid < 32) {
        int w = wsum[tid];
        #pragma unroll
        for (int d = 1; d < 32; d <<= 1) {
            int y = __shfl_up_sync(0xffffffffu, w, d);
            if (tid >= d) w += y;
        }
        wsum[tid] = w;
    }
    __syncthreads();
    int warpoff = (tid >= 32) ? wsum[(tid >> 5) - 1] : 0;
    int excl = s_chunkoff + warpoff + (x - s);

    #pragma unroll
    for (int j = 0; j < 4; j++) {
        int i = base + j;
        if (i < n) {
            g_rowptr[i] = excl;
            g_cursor[i] = excl;
            g_nd[i] = rsqrtf(fmaxf((float)v[j], 1.0f));
        }
        excl += v[j];
    }
}

__global__ void csr_kernel(const int* __restrict__ src, const int* __restrict__ dst, int e) {
    int i4 = (blockIdx.x * blockDim.x + threadIdx.x) * 4;
    if (i4 + 3 < e) {
        int4 d = *(const int4*)(dst + i4);
        int4 s = *(const int4*)(src + i4);
        g_srcsorted[atomicAdd(&g_cursor[d.x], 1)] = s.x;
        g_srcsorted[atomicAdd(&g_cursor[d.y], 1)] = s.y;
        g_srcsorted[atomicAdd(&g_cursor[d.z], 1)] = s.z;
        g_srcsorted[atomicAdd(&g_cursor[d.w], 1)] = s.w;
    } else {
        for (int i = i4; i < e; i++)
            g_srcsorted[atomicAdd(&g_cursor[dst[i]], 1)] = src[i];
    }
}

// ---------------- packed-f32x2 GEMM, row-paired accumulators ----------------
// C[n x 64] = A[n x K] @ B[K x 64]
// 128x64 tile, 128 threads, 8x8 micro-tile. A pairs free from transposed smem;
// B duplicated in registers (mov.b64). Inner loop: 32 fma.rn.f32x2 / thread / k.
// mode 0: C = ns[row] * (A@B);  mode 1: C = (beta ? C : 0) + A@B
template <int K>
__global__ void __launch_bounds__(128, 4) gemm_pk(
    const float* __restrict__ A, int lda,
    const float* __restrict__ B,
    float* __restrict__ C,
    int mode, int beta, int n)
{
    constexpr int KC = 16;
    constexpr int AST = 128 + 4;
    __shared__ float As[KC][AST];     // transposed: [k][row]
    __shared__ float Bs[KC][64 + 4];  // [k][col]

    const int tid = threadIdx.x;
    const int tr = tid >> 3;     // 0..15 -> rows tr*8 .. tr*8+7
    const int tcv = tid & 7;     // 0..7  -> cols tcv*8 .. tcv*8+7
    const int row0 = blockIdx.x * 128;

    unsigned long long acc[4][8];   // [row-pair][col]
    #pragma unroll
    for (int rp = 0; rp < 4; rp++)
        #pragma unroll
        for (int c = 0; c < 8; c++) acc[rp][c] = 0ULL;

    for (int kc = 0; kc < K; kc += KC) {
        // stage A: 128 rows x KC, transposed (512 float4 loads, 4/thread)
        #pragma unroll
        for (int i = 0; i < 4; i++) {
            int flat = tid + i * 128;
            int row = flat >> 2;
            int k4 = flat & 3;
            float4 v = make_float4(0.f, 0.f, 0.f, 0.f);
            int gr = row0 + row;
            if (gr < n) v = *(const float4*)(A + (size_t)gr * lda + kc + k4 * 4);
            As[k4 * 4 + 0][row] = v.x;
            As[k4 * 4 + 1][row] = v.y;
            As[k4 * 4 + 2][row] = v.z;
            As[k4 * 4 + 3][row] = v.w;
        }
        // stage B: KC x 64 (256 float4, 2/thread)
        #pragma unroll
        for (int i = 0; i < 2; i++) {
            int flat = tid + i * 128;
            int k = flat >> 4;
            int c4 = flat & 15;
            *(float4*)&Bs[k][c4 * 4] = *(const float4*)(B + (size_t)(kc + k) * 64 + c4 * 4);
        }
        __syncthreads();

        #pragma unroll
        for (int k = 0; k < KC; k++) {
            // A row pairs, packed for free
            ulonglong2 aA = *(const ulonglong2*)&As[k][tr * 8];      // rows (0,1),(2,3)
            ulonglong2 aB = *(const ulonglong2*)&As[k][tr * 8 + 4];  // rows (4,5),(6,7)
            unsigned long long ap[4] = {aA.x, aA.y, aB.x, aB.y};
            // B cols, duplicate scalars into (b,b)
            float4 b0 = *(const float4*)&Bs[k][tcv * 8];
            float4 b1 = *(const float4*)&Bs[k][tcv * 8 + 4];
            unsigned long long bd[8] = {dup2(b0.x), dup2(b0.y), dup2(b0.z), dup2(b0.w),
                                        dup2(b1.x), dup2(b1.y), dup2(b1.z), dup2(b1.w)};
            #pragma unroll
            for (int rp = 0; rp < 4; rp++)
                #pragma unroll
                for (int c = 0; c < 8; c++)
                    fma2(acc[rp][c], ap[rp], bd[c]);
        }
        __syncthreads();
    }

    // epilogue: acc[rp][c] = rows (tr*8+2rp, tr*8+2rp+1), col tcv*8+c
    #pragma unroll
    for (int rp = 0; rp < 4; rp++) {
        float2 p[8];
        #pragma unroll
        for (int c = 0; c < 8; c++) p[c] = unpk(acc[rp][c]);
        #pragma unroll
        for (int half = 0; half < 2; half++) {
            int gr = row0 + tr * 8 + 2 * rp + half;
            if (gr >= n) continue;
            float4 v0, v1;
            if (half == 0) {
                v0 = make_float4(p[0].x, p[1].x, p[2].x, p[3].x);
                v1 = make_float4(p[4].x, p[5].x, p[6].x, p[7].x);
            } else {
                v0 = make_float4(p[0].y, p[1].y, p[2].y, p[3].y);
                v1 = make_float4(p[4].y, p[5].y, p[6].y, p[7].y);
            }
            float* cp = C + (size_t)gr * 64 + tcv * 8;
            if (mode == 0) {
                float s = g_ns[gr];
                v0.x *= s; v0.y *= s; v0.z *= s; v0.w *= s;
                v1.x *= s; v1.y *= s; v1.z *= s; v1.w *= s;
            } else if (beta) {
                float4 o0 = *(const float4*)cp;
                float4 o1 = *(const float4*)(cp + 4);
                v0.x += o0.x; v0.y += o0.y; v0.z += o0.z; v0.w += o0.w;
                v1.x += o1.x; v1.y += o1.y; v1.z += o1.z; v1.w += o1.w;
            }
            *(float4*)cp = v0;
            *(float4*)(cp + 4) = v1;
        }
    }
}

// ---------------- CSR gather-aggregate (fused pointwise epilogue) ----------------
template <bool NS, bool RELU>
__global__ void __launch_bounds__(256) aggregate_kernel(
    const float* __restrict__ tin, float* __restrict__ hout,
    const float* __restrict__ bias, int n)
{
    int g = blockIdx.x * 256 + threadIdx.x;
    int node = g >> 4;
    int lane = g & 15;
    if (node >= n) return;
    int beg = g_rowptr[node];
    int end = g_rowptr[node + 1];
    float4 acc = make_float4(0.f, 0.f, 0.f, 0.f);

    int e = beg;
    for (; e + 4 <= end; e += 4) {
        int s0 = __ldg(&g_srcsorted[e + 0]);
        int s1 = __ldg(&g_srcsorted[e + 1]);
        int s2 = __ldg(&g_srcsorted[e + 2]);
        int s3 = __ldg(&g_srcsorted[e + 3]);
        float4 v0 = *(const float4*)(tin + (size_t)s0 * 64 + lane * 4);
        float4 v1 = *(const float4*)(tin + (size_t)s1 * 64 + lane * 4);
        float4 v2 = *(const float4*)(tin + (size_t)s2 * 64 + lane * 4);
        float4 v3 = *(const float4*)(tin + (size_t)s3 * 64 + lane * 4);
        if (NS) {
            float w0 = __ldg(&g_ns[s0]);
            float w1 = __ldg(&g_ns[s1]);
            float w2 = __ldg(&g_ns[s2]);
            float w3 = __ldg(&g_ns[s3]);
            acc.x = fmaf(v0.x, w0, acc.x); acc.y = fmaf(v0.y, w0, acc.y);
            acc.z = fmaf(v0.z, w0, acc.z); acc.w = fmaf(v0.w, w0, acc.w);
            acc.x = fmaf(v1.x, w1, acc.x); acc.y = fmaf(v1.y, w1, acc.y);
            acc.z = fmaf(v1.z, w1, acc.z); acc.w = fmaf(v1.w, w1, acc.w);
            acc.x = fmaf(v2.x, w2, acc.x); acc.y = fmaf(v2.y, w2, acc.y);
            acc.z = fmaf(v2.z, w2, acc.z); acc.w = fmaf(v2.w, w2, acc.w);
            acc.x = fmaf(v3.x, w3, acc.x); acc.y = fmaf(v3.y, w3, acc.y);
            acc.z = fmaf(v3.z, w3, acc.z); acc.w = fmaf(v3.w, w3, acc.w);
        } else {
            acc.x += v0.x + v1.x + v2.x + v3.x;
            acc.y += v0.y + v1.y + v2.y + v3.y;
            acc.z += v0.z + v1.z + v2.z + v3.z;
            acc.w += v0.w + v1.w + v2.w + v3.w;
        }
    }
    for (; e < end; e++) {
        int s = __ldg(&g_srcsorted[e]);
        float4 v = *(const float4*)(tin + (size_t)s * 64 + lane * 4);
        if (NS) {
            float w = __ldg(&g_ns[s]);
            acc.x = fmaf(v.x, w, acc.x); acc.y = fmaf(v.y, w, acc.y);
            acc.z = fmaf(v.z, w, acc.z); acc.w = fmaf(v.w, w, acc.w);
        } else {
            acc.x += v.x; acc.y += v.y; acc.z += v.z; acc.w += v.w;
        }
    }

    float4 bb = *(const float4*)(bias + lane * 4);
    float4 o;
    if (RELU) {
        float ndv = g_nd[node];
        o.x = fmaxf(fmaf(acc.x, ndv, bb.x), 0.f);
        o.y = fmaxf(fmaf(acc.y, ndv, bb.y), 0.f);
        o.z = fmaxf(fmaf(acc.z, ndv, bb.z), 0.f);
        o.w = fmaxf(fmaf(acc.w, ndv, bb.w), 0.f);
    } else {
        o.x = acc.x + bb.x; o.y = acc.y + bb.y;
        o.z = acc.z + bb.z; o.w = acc.w + bb.w;
    }
    *(float4*)(hout + (size_t)node * 64 + lane * 4) = o;
}

// ---------------- host ----------------
extern "C" void kernel_launch(void* const* d_in, const int* in_sizes, int n_in,
                              void* d_out, int out_size)
{
    const float* feats = (const float*)d_in[0];
    const int*   src   = (const int*)d_in[1];
    const int*   dst   = (const int*)d_in[2];
    const float* W[5];
    const float* b[5];
    for (int i = 0; i < 5; i++) {
        W[i] = (const float*)d_in[3 + 2 * i];
        b[i] = (const float*)d_in[4 + 2 * i];
    }
    const float* Wout = (const float*)d_in[13];
    const float* bout = (const float*)d_in[14];
    float* out = (float*)d_out;

    int n = in_sizes[0] / FIN;   // 100000
    int e = in_sizes[1];         // 1600000

    float *t, *proj, *hb[3];
    cudaGetSymbolAddress((void**)&t, g_t);
    cudaGetSymbolAddress((void**)&proj, g_proj);
    cudaGetSymbolAddress((void**)&hb[0], g_h0);
    cudaGetSymbolAddress((void**)&hb[1], g_h1);
    cudaGetSymbolAddress((void**)&hb[2], g_h2);

    static cudaStream_t side = nullptr;
    static cudaEvent_t evFork, evPre, evH[6], evP[5];
    if (!side) {
        cudaStreamCreateWithFlags(&side, cudaStreamNonBlocking);
        cudaEventCreateWithFlags(&evFork, cudaEventDisableTiming);
        cudaEventCreateWithFlags(&evPre, cudaEventDisableTiming);
        for (int i = 0; i < 6; i++) cudaEventCreateWithFlags(&evH[i], cudaEventDisableTiming);
        for (int i = 0; i < 5; i++) cudaEventCreateWithFlags(&evP[i], cudaEventDisableTiming);
    }

    int nb256 = (n + 255) / 256;
    int eb4 = (e / 4 + 255) / 256;     // 4 edges/thread
    int gemm_blocks = (n + 127) / 128;
    int agg_blocks = (n * 16 + 255) / 256;
    int nchunk = (n + CHUNK - 1) / CHUNK;

    // ---- fork: indeg chain on side; outdeg chain + GEMM L0 on main ----
    cudaEventRecord(evFork, 0);
    cudaStreamWaitEvent(side, evFork, 0);

    // side: indeg -> rowptr/cursor/nd -> csr
    zero_in_kernel<<<nb256, 256, 0, side>>>(n);
    count_in_kernel<<<eb4, 256, 0, side>>>(dst, e);
    chunksum_kernel<<<nchunk, 1024, 0, side>>>(n);
    rescan_kernel<<<nchunk, 1024, 0, side>>>(n);
    csr_kernel<<<eb4, 256, 0, side>>>(src, dst, e);
    cudaEventRecord(evPre, side);

    // main: outdeg -> ns, then t = feats @ W0 (ns applied per-edge in agg L0)
    zero_out_kernel<<<nb256, 256>>>(n);
    count_out_kernel<<<eb4, 256>>>(src, e);
    ns_kernel<<<nb256, 256>>>(n);
    gemm_pk<FIN><<<gemm_blocks, 128>>>(feats, FIN, W[0], t, 1, 0, n);

    // join, then layer-0 aggregate: h = relu(nd * sum(ns[s]*t[s]) + b0)
    cudaStreamWaitEvent(0, evPre, 0);
    aggregate_kernel<true, true><<<agg_blocks, 256>>>(t, hb[0], b[0], n);
    cudaEventRecord(evH[1], 0);

    // layers 1..4
    for (int l = 1; l < 5; l++) {
        float* h_in = hb[(l - 1) % 3];
        float* h_out = hb[l % 3];

        // side: proj (+)= h_in @ Wout_{l-1}
        cudaStreamWaitEvent(side, evH[l], 0);
        gemm_pk<HID><<<gemm_blocks, 128, 0, side>>>(
            h_in, HID, Wout + (size_t)(l - 1) * HID * 64, proj, 1, (l > 1) ? 1 : 0, n);
        cudaEventRecord(evP[l - 1], side);

        // main: t = ns * (h_in @ W_l); then aggregate
        gemm_pk<HID><<<gemm_blocks, 128>>>(h_in, HID, W[l], t, 0, 0, n);
        if (l >= 3) cudaStreamWaitEvent(0, evP[l - 3], 0);
        aggregate_kernel<false, true><<<agg_blocks, 256>>>(t, h_out, b[l], n);
        cudaEventRecord(evH[l + 1], 0);
    }

    // side: proj += h5 @ Wout_4
    float* h5 = hb[4 % 3];
    cudaStreamWaitEvent(side, evH[5], 0);
    gemm_pk<HID><<<gemm_blocks, 128, 0, side>>>(
        h5, HID, Wout + (size_t)4 * HID * 64, proj, 1, 1, n);
    cudaEventRecord(evP[4], side);

    // main: out = sum(proj[src]) + bout
    cudaStreamWaitEvent(0, evP[4], 0);
    aggregate_kernel<false, false><<<agg_blocks, 256>>>(proj, out, bout, n);
}